// round 12
// baseline (speedup 1.0000x reference)
#include <cuda_runtime.h>
#include <cuda_fp16.h>
#include <math.h>
#include <stddef.h>
#include <stdint.h>

#define DIMD 1024
#define BB 2
#define LLEN 2048
#define MTOK 4096
#define NHEAD 16
#define HD 64
#define FFD 4096
#define QKVN 3072
#define NPERS 296                      // 2 CTAs/SM * 148 SMs

typedef __half f16;

// ---------------- scratch (device globals; no allocations allowed) ----------
__device__ f16  g_nx[MTOK * DIMD];
__device__ f16  g_wqkv[QKVN * DIMD];
__device__ f16  g_wo[DIMD * DIMD];
__device__ f16  g_w1[FFD * DIMD];
__device__ f16  g_w2[DIMD * FFD];
__device__ f16  g_qkv[(size_t)MTOK * QKVN];
__device__ f16  g_attn[MTOK * DIMD];
__device__ float g_x1[MTOK * DIMD];
__device__ f16  g_h[(size_t)MTOK * FFD];

// ---------------- helpers -----------------------------------------------------
__device__ __forceinline__ uint32_t cvta_s(const void* p) {
    return (uint32_t)__cvta_generic_to_shared(p);
}
__device__ __forceinline__ void cp16(uint32_t dst, const void* src) {
    asm volatile("cp.async.cg.shared.global [%0], [%1], 16;" :: "r"(dst), "l"(src) : "memory");
}
__device__ __forceinline__ void ldm_x4(uint32_t addr, uint32_t& r0, uint32_t& r1,
                                       uint32_t& r2, uint32_t& r3) {
    asm volatile("ldmatrix.sync.aligned.m8n8.x4.shared.b16 {%0,%1,%2,%3}, [%4];"
                 : "=r"(r0), "=r"(r1), "=r"(r2), "=r"(r3) : "r"(addr));
}
__device__ __forceinline__ void ldm_x4_t(uint32_t addr, uint32_t& r0, uint32_t& r1,
                                         uint32_t& r2, uint32_t& r3) {
    asm volatile("ldmatrix.sync.aligned.m8n8.x4.trans.shared.b16 {%0,%1,%2,%3}, [%4];"
                 : "=r"(r0), "=r"(r1), "=r"(r2), "=r"(r3) : "r"(addr));
}
__device__ __forceinline__ void mma_f16(float& d0, float& d1, float& d2, float& d3,
                                        uint32_t a0, uint32_t a1, uint32_t a2, uint32_t a3,
                                        uint32_t b0, uint32_t b1) {
    asm volatile(
        "mma.sync.aligned.m16n8k16.row.col.f32.f16.f16.f32 "
        "{%0,%1,%2,%3}, {%4,%5,%6,%7}, {%8,%9}, {%0,%1,%2,%3};"
        : "+f"(d0), "+f"(d1), "+f"(d2), "+f"(d3)
        : "r"(a0), "r"(a1), "r"(a2), "r"(a3), "r"(b0), "r"(b1));
}
__device__ __forceinline__ uint32_t pack2f(float a, float b) {
    __half2 h = __floats2half2_rn(a, b);
    return *reinterpret_cast<uint32_t*>(&h);
}
__device__ __forceinline__ void wait_n(int wg) {
    if (wg >= 2)      asm volatile("cp.async.wait_group 2;" ::: "memory");
    else if (wg == 1) asm volatile("cp.async.wait_group 1;" ::: "memory");
    else              asm volatile("cp.async.wait_group 0;" ::: "memory");
}

// ---------------- prep: weight converts + LN1 in ONE launch -------------------
// blocks [0,12288): weight convert (1024 elems each); [12288,16384): LN1 rows
__global__ __launch_bounds__(256) void prep_kernel(
    const float* __restrict__ wq, const float* __restrict__ wk,
    const float* __restrict__ wv, const float* __restrict__ wo,
    const float* __restrict__ w1, const float* __restrict__ w2,
    f16* __restrict__ dqkv, f16* __restrict__ dwo,
    f16* __restrict__ dw1, f16* __restrict__ dw2,
    const float* __restrict__ x, const float* __restrict__ g1,
    const float* __restrict__ b1, f16* __restrict__ nx)
{
    int blk = blockIdx.x;
    int tid = threadIdx.x;
    if (blk < 12288) {
        const float* src;
        f16* dst;
        size_t off;
        const size_t DD = (size_t)DIMD * DIMD;
        if (blk < 1024)      { src = wq; dst = dqkv;          off = (size_t)blk * 1024; }
        else if (blk < 2048) { src = wk; dst = dqkv + DD;     off = (size_t)(blk - 1024) * 1024; }
        else if (blk < 3072) { src = wv; dst = dqkv + 2 * DD; off = (size_t)(blk - 2048) * 1024; }
        else if (blk < 4096) { src = wo; dst = dwo;           off = (size_t)(blk - 3072) * 1024; }
        else if (blk < 8192) { src = w1; dst = dw1;           off = (size_t)(blk - 4096) * 1024; }
        else                 { src = w2; dst = dw2;           off = (size_t)(blk - 8192) * 1024; }
        size_t i = off + tid * 4;
        float4 v = *(const float4*)(src + i);
        f16 h4[4];
        h4[0] = __float2half_rn(v.x); h4[1] = __float2half_rn(v.y);
        h4[2] = __float2half_rn(v.z); h4[3] = __float2half_rn(v.w);
        *(uint2*)(dst + i) = *(uint2*)h4;
        return;
    }
    // LN1
    int row = blk - 12288;
    float4 v = ((const float4*)(x + (size_t)row * DIMD))[tid];
    float s  = v.x + v.y + v.z + v.w;
    float sq = v.x * v.x + v.y * v.y + v.z * v.z + v.w * v.w;
    #pragma unroll
    for (int o = 16; o; o >>= 1) {
        s  += __shfl_xor_sync(0xFFFFFFFFu, s,  o);
        sq += __shfl_xor_sync(0xFFFFFFFFu, sq, o);
    }
    __shared__ float red[8], red2[8], mu_s, rs_s;
    int w = tid >> 5, ln = tid & 31;
    if (ln == 0) { red[w] = s; red2[w] = sq; }
    __syncthreads();
    if (tid == 0) {
        float ts = 0.f, tq = 0.f;
        #pragma unroll
        for (int i = 0; i < 8; i++) { ts += red[i]; tq += red2[i]; }
        float mu  = ts * (1.0f / DIMD);
        float var = tq * (1.0f / DIMD) - mu * mu;
        mu_s = mu;
        rs_s = rsqrtf(var + 1e-5f);
    }
    __syncthreads();
    float mu = mu_s, rs = rs_s;
    float4 gv = ((const float4*)g1)[tid];
    float4 bv = ((const float4*)b1)[tid];
    f16 h4[4];
    h4[0] = __float2half_rn((v.x - mu) * rs * gv.x + bv.x);
    h4[1] = __float2half_rn((v.y - mu) * rs * gv.y + bv.y);
    h4[2] = __float2half_rn((v.z - mu) * rs * gv.z + bv.z);
    h4[3] = __float2half_rn((v.w - mu) * rs * gv.w + bv.w);
    *(uint2*)(nx + (size_t)row * DIMD + tid * 4) = *(uint2*)h4;
}

// ---------------- LayerNorm (standalone, LN2) ---------------------------------
__global__ __launch_bounds__(256) void ln_kernel(
    const float* __restrict__ x, const float* __restrict__ g,
    const float* __restrict__ b, f16* __restrict__ ohi)
{
    int row = blockIdx.x;
    int tid = threadIdx.x;
    float4 v = ((const float4*)(x + (size_t)row * DIMD))[tid];
    float s  = v.x + v.y + v.z + v.w;
    float sq = v.x * v.x + v.y * v.y + v.z * v.z + v.w * v.w;
    #pragma unroll
    for (int o = 16; o; o >>= 1) {
        s  += __shfl_xor_sync(0xFFFFFFFFu, s,  o);
        sq += __shfl_xor_sync(0xFFFFFFFFu, sq, o);
    }
    __shared__ float red[8], red2[8], mu_s, rs_s;
    int w = tid >> 5, ln = tid & 31;
    if (ln == 0) { red[w] = s; red2[w] = sq; }
    __syncthreads();
    if (tid == 0) {
        float ts = 0.f, tq = 0.f;
        #pragma unroll
        for (int i = 0; i < 8; i++) { ts += red[i]; tq += red2[i]; }
        float mu  = ts * (1.0f / DIMD);
        float var = tq * (1.0f / DIMD) - mu * mu;
        mu_s = mu;
        rs_s = rsqrtf(var + 1e-5f);
    }
    __syncthreads();
    float mu = mu_s, rs = rs_s;
    float4 gv = ((const float4*)g)[tid];
    float4 bv = ((const float4*)b)[tid];
    f16 h4[4];
    h4[0] = __float2half_rn((v.x - mu) * rs * gv.x + bv.x);
    h4[1] = __float2half_rn((v.y - mu) * rs * gv.y + bv.y);
    h4[2] = __float2half_rn((v.z - mu) * rs * gv.z + bv.z);
    h4[3] = __float2half_rn((v.w - mu) * rs * gv.w + bv.w);
    *(uint2*)(ohi + (size_t)row * DIMD + tid * 4) = *(uint2*)h4;
}

// ---------------- persistent HMMA fp16 GEMM (BK=64, f32 accum) ----------------
// EPI: 1=f32+res  2=f32+bias+res  3=bias+gelu->f16  4=f16
#define SSTRIDE 72
#define TILE_BYTES (128 * SSTRIDE * 2)
#define STAGE_BYTES (2 * TILE_BYTES)
#define NSTAGE 3
#define SMEM_DYN (NSTAGE * STAGE_BYTES)

template <int EPI>
__global__ __launch_bounds__(256) void gemm_tc(
    const f16* __restrict__ A, const f16* __restrict__ B,
    const float* __restrict__ bias, const float* __restrict__ res,
    float* __restrict__ Cf, f16* __restrict__ Ch,
    int M, int N, int K)
{
    extern __shared__ __align__(128) char smem[];
    uint32_t sbase = cvta_s(smem);
    int tid  = threadIdx.x;
    int lane = tid & 31;
    int w    = tid >> 5;
    int warpM = w & 3, warpN = w >> 2;

    const int C = K >> 6;
    const int ntx = N >> 7;
    const int ntiles = (M >> 7) * ntx;

    auto load_chunk = [&](int m0, int n0, int c, int stage) {
        int k0 = c << 6;
        uint32_t abuf = sbase + stage * STAGE_BYTES;
        uint32_t bbuf = abuf + TILE_BYTES;
        #pragma unroll
        for (int i = 0; i < 4; i++) {
            int idx = tid + i * 256;
            int row = idx >> 3;
            int cg  = idx & 7;
            uint32_t doff = row * (SSTRIDE * 2) + cg * 16;
            cp16(abuf + doff, A + (size_t)(m0 + row) * K + k0 + cg * 8);
            cp16(bbuf + doff, B + (size_t)(n0 + row) * K + k0 + cg * 8);
        }
        asm volatile("cp.async.commit_group;");
    };

    int lrow = lane & 15;
    int lcol = (lane >> 4) << 3;

    int t = blockIdx.x;
    if (t >= ntiles) return;
    {
        int m0 = (t / ntx) << 7, n0 = (t % ntx) << 7;
        load_chunk(m0, n0, 0, 0);
        load_chunk(m0, n0, 1, 1);
        load_chunk(m0, n0, 2, 2);
    }

    for (; t < ntiles; t += gridDim.x) {
        int m0 = (t / ntx) << 7, n0 = (t % ntx) << 7;

        float acc[2][8][4];
        #pragma unroll
        for (int i = 0; i < 2; i++)
            #pragma unroll
            for (int j = 0; j < 8; j++)
                #pragma unroll
                for (int tt = 0; tt < 4; tt++) acc[i][j][tt] = 0.f;

        for (int c = 0; c < C; c++) {
            wait_n(C - 1 - c);            // chunk c guaranteed complete
            __syncthreads();
            int stage = c - (c / NSTAGE) * NSTAGE;
            uint32_t abuf = sbase + stage * STAGE_BYTES;
            uint32_t bbuf = abuf + TILE_BYTES;

            #pragma unroll
            for (int ks = 0; ks < 4; ks++) {
                int kk = ks * 16;
                uint32_t a[2][4];
                #pragma unroll
                for (int mi = 0; mi < 2; mi++) {
                    int r = warpM * 32 + mi * 16 + lrow;
                    uint32_t addr = abuf + (r * SSTRIDE + kk + lcol) * 2;
                    ldm_x4(addr, a[mi][0], a[mi][1], a[mi][2], a[mi][3]);
                }
                uint32_t bfr[8][2];
                #pragma unroll
                for (int nj = 0; nj < 4; nj++) {
                    int r = warpN * 64 + nj * 16 + lrow;
                    uint32_t addr = bbuf + (r * SSTRIDE + kk + lcol) * 2;
                    uint32_t b0, b1, b2, b3;
                    ldm_x4(addr, b0, b1, b2, b3);
                    bfr[nj * 2 + 0][0] = b0; bfr[nj * 2 + 0][1] = b2;
                    bfr[nj * 2 + 1][0] = b1; bfr[nj * 2 + 1][1] = b3;
                }
                #pragma unroll
                for (int mi = 0; mi < 2; mi++)
                    #pragma unroll
                    for (int nt = 0; nt < 8; nt++)
                        mma_f16(acc[mi][nt][0], acc[mi][nt][1], acc[mi][nt][2], acc[mi][nt][3],
                                a[mi][0], a[mi][1], a[mi][2], a[mi][3],
                                bfr[nt][0], bfr[nt][1]);
            }
            __syncthreads();
            if (c + NSTAGE < C) load_chunk(m0, n0, c + NSTAGE, stage);
        }

        // prime next tile BEFORE epilogue (loads overlap stores)
        int tn = t + gridDim.x;
        if (tn < ntiles) {
            int m0n = (tn / ntx) << 7, n0n = (tn % ntx) << 7;
            load_chunk(m0n, n0n, 0, 0);
            load_chunk(m0n, n0n, 1, 1);
            load_chunk(m0n, n0n, 2, 2);
        }

        int rbase = m0 + warpM * 32 + (lane >> 2);
        int cbase = n0 + warpN * 64 + (lane & 3) * 2;
        #pragma unroll
        for (int mi = 0; mi < 2; mi++) {
            #pragma unroll
            for (int half = 0; half < 2; half++) {
                int row = rbase + mi * 16 + half * 8;
                size_t gr = (size_t)row * N;
                #pragma unroll
                for (int nt = 0; nt < 8; nt++) {
                    int col = cbase + nt * 8;
                    float v0 = acc[mi][nt][half * 2 + 0];
                    float v1 = acc[mi][nt][half * 2 + 1];
                    if (EPI == 2 || EPI == 3) { v0 += bias[col]; v1 += bias[col + 1]; }
                    if (EPI == 3 || EPI == 4) {
                        if (EPI == 3) {
                            v0 = 0.5f * v0 * (1.f + erff(v0 * 0.70710678118654752f));
                            v1 = 0.5f * v1 * (1.f + erff(v1 * 0.70710678118654752f));
                        }
                        *(uint32_t*)(Ch + gr + col) = pack2f(v0, v1);
                    } else {
                        float2 rr = *(const float2*)(res + gr + col);
                        v0 += rr.x; v1 += rr.y;
                        *(float2*)(Cf + gr + col) = make_float2(v0, v1);
                    }
                }
            }
        }
    }
}

// ---------------- HMMA flash attention: fixed-shift softmax -------------------
#define KSTRB 144
#define FTILE (64 * KSTRB)
#define FS_Q0   0
#define FS_STG  FTILE
#define FS_BIAS (FS_STG + 2 * 2 * FTILE)
#define FSMEM   (FS_BIAS + LLEN * 4)
#define C2EXP   0.1803368801111204f
#define LOG2E   1.4426950408889634f

__global__ __launch_bounds__(128) void flash_tc(
    const f16* __restrict__ qkv, const unsigned char* __restrict__ smask,
    f16* __restrict__ oh)
{
    extern __shared__ __align__(128) char sm[];
    uint32_t sb = cvta_s(sm);
    float* biasArr = (float*)(sm + FS_BIAS);
    int qt = gridDim.x - 1 - blockIdx.x;
    int h = blockIdx.y, b = blockIdx.z;
    int tid = threadIdx.x, lane = tid & 31, w = tid >> 5;
    int lrow = lane & 15, lcol = (lane >> 4) << 3;
    size_t tok0 = (size_t)b * LLEN;
    int hoff = h * HD;

    #pragma unroll
    for (int i = 0; i < 4; i++) {
        int slot = tid + i * 128;
        int r    = slot >> 3;
        int seg  = slot & 7;
        const f16* src = qkv + (tok0 + qt * 64 + r) * QKVN + hoff + seg * 8;
        cp16(sb + FS_Q0 + r * KSTRB + seg * 16, src);
    }
    asm volatile("cp.async.commit_group;");

    for (int i = tid; i < LLEN; i += 128) {
        float m = smask[tok0 + i] ? -10003.f : -3.f;
        biasArr[i] = m * LOG2E;
    }

    auto load_stage = [&](int kt, int s) {
        uint32_t base = sb + FS_STG + s * (2 * FTILE);
        int k0 = kt * 64;
        #pragma unroll
        for (int i = 0; i < 8; i++) {
            int slot = tid + i * 128;
            int comp = slot >> 9;
            int r    = (slot >> 3) & 63;
            int seg  = slot & 7;
            int coff = comp ? 2 * DIMD : DIMD;
            const f16* src = qkv + (tok0 + k0 + r) * QKVN + coff + hoff + seg * 8;
            cp16(base + comp * FTILE + r * KSTRB + seg * 16, src);
        }
        asm volatile("cp.async.commit_group;");
    };

    load_stage(0, 0);

    asm volatile("cp.async.wait_group 1;" ::: "memory");
    __syncthreads();

    uint32_t qf[4][4];
    #pragma unroll
    for (int kc = 0; kc < 4; kc++) {
        uint32_t addr = sb + FS_Q0 + (w * 16 + lrow) * KSTRB + (kc * 16 + lcol) * 2;
        ldm_x4(addr, qf[kc][0], qf[kc][1], qf[kc][2], qf[kc][3]);
    }

    float O[8][4];
    #pragma unroll
    for (int nt = 0; nt < 8; nt++)
        #pragma unroll
        for (int t = 0; t < 4; t++) O[nt][t] = 0.f;
    float l0r = 0.f, l1r = 0.f;

    int colb = 2 * (lane & 3);
    int qrow0 = qt * 64 + w * 16 + (lane >> 2);
    int qrow1 = qrow0 + 8;

    for (int kt = 0; kt <= qt; kt++) {
        int s = kt & 1;
        if (kt < qt) {
            load_stage(kt + 1, s ^ 1);
            asm volatile("cp.async.wait_group 1;" ::: "memory");
        } else {
            asm volatile("cp.async.wait_group 0;" ::: "memory");
        }
        __syncthreads();

        uint32_t KHB = sb + FS_STG + s * (2 * FTILE);
        uint32_t VHB = KHB + FTILE;
        bool diag = (kt == qt);

        float S[8][4];
        #pragma unroll
        for (int nt = 0; nt < 8; nt++)
            #pragma unroll
            for (int t = 0; t < 4; t++) S[nt][t] = 0.f;

        #pragma unroll
        for (int kc = 0; kc < 4; kc++) {
            uint32_t bh[8][2];
            #pragma unroll
            for (int nj = 0; nj < 4; nj++) {
                uint32_t addr = KHB + (nj * 16 + lrow) * KSTRB + (kc * 16 + lcol) * 2;
                uint32_t r0, r1, r2, r3;
                ldm_x4(addr, r0, r1, r2, r3);
                bh[nj * 2][0] = r0; bh[nj * 2][1] = r2;
                bh[nj * 2 + 1][0] = r1; bh[nj * 2 + 1][1] = r3;
            }
            #pragma unroll
            for (int nt = 0; nt < 8; nt++)
                mma_f16(S[nt][0], S[nt][1], S[nt][2], S[nt][3],
                        qf[kc][0], qf[kc][1], qf[kc][2], qf[kc][3],
                        bh[nt][0], bh[nt][1]);
        }

        uint32_t ph[8][2];
        #pragma unroll
        for (int nt = 0; nt < 8; nt++) {
            int c0 = kt * 64 + nt * 8 + colb;
            float2 bz = *(const float2*)&biasArr[c0];
            float p0 = exp2f(fmaf(S[nt][0], C2EXP, bz.x));
            float p1 = exp2f(fmaf(S[nt][1], C2EXP, bz.y));
            float p2 = exp2f(fmaf(S[nt][2], C2EXP, bz.x));
            float p3 = exp2f(fmaf(S[nt][3], C2EXP, bz.y));
            if (diag) {
                p0 = (c0     <= qrow0) ? p0 : 0.f;
                p1 = (c0 + 1 <= qrow0) ? p1 : 0.f;
                p2 = (c0     <= qrow1) ? p2 : 0.f;
                p3 = (c0 + 1 <= qrow1) ? p3 : 0.f;
            }
            l0r += p0 + p1;
            l1r += p2 + p3;
            ph[nt][0] = pack2f(p0, p1);
            ph[nt][1] = pack2f(p2, p3);
        }

        #pragma unroll
        for (int kc = 0; kc < 4; kc++) {
            uint32_t ah0 = ph[2 * kc][0], ah1 = ph[2 * kc][1];
            uint32_t ah2 = ph[2 * kc + 1][0], ah3 = ph[2 * kc + 1][1];
            #pragma unroll
            for (int dn = 0; dn < 4; dn++) {
                int g = lane >> 3, j = lane & 7;
                uint32_t addr = VHB + (kc * 16 + ((g & 1) ? 8 : 0) + j) * KSTRB
                              + (dn * 16 + ((g >> 1) ? 8 : 0)) * 2;
                uint32_t vh0, vh1, vh2, vh3;
                ldm_x4_t(addr, vh0, vh1, vh2, vh3);
                mma_f16(O[2 * dn][0], O[2 * dn][1], O[2 * dn][2], O[2 * dn][3],
                        ah0, ah1, ah2, ah3, vh0, vh1);
                mma_f16(O[2 * dn + 1][0], O[2 * dn + 1][1], O[2 * dn + 1][2], O[2 * dn + 1][3],
                        ah0, ah1, ah2, ah3, vh2, vh3);
            }
        }
        __syncthreads();
    }

    l0r += __shfl_xor_sync(0xFFFFFFFFu, l0r, 1);
    l0r += __shfl_xor_sync(0xFFFFFFFFu, l0r, 2);
    l1r += __shfl_xor_sync(0xFFFFFFFFu, l1r, 1);
    l1r += __shfl_xor_sync(0xFFFFFFFFu, l1r, 2);
    float i0 = 1.f / l0r, i1 = 1.f / l1r;
    size_t t0k = tok0 + qt * 64 + w * 16 + (lane >> 2);
    size_t t1k = t0k + 8;
    #pragma unroll
    for (int nt = 0; nt < 8; nt++) {
        int col = hoff + nt * 8 + colb;
        *(uint32_t*)(oh + t0k * DIMD + col) = pack2f(O[nt][0] * i0, O[nt][1] * i0);
        *(uint32_t*)(oh + t1k * DIMD + col) = pack2f(O[nt][2] * i1, O[nt][3] * i1);
    }
}

// ---------------- driver -----------------------------------------------------
extern "C" void kernel_launch(void* const* d_in, const int* in_sizes, int n_in,
                              void* d_out, int out_size)
{
    const float* x          = (const float*)d_in[0];
    const unsigned char* sm = (const unsigned char*)d_in[1];
    const float* wq         = (const float*)d_in[2];
    const float* wk         = (const float*)d_in[3];
    const float* wv         = (const float*)d_in[4];
    const float* wo         = (const float*)d_in[5];
    const float* g1         = (const float*)d_in[6];
    const float* b1         = (const float*)d_in[7];
    const float* g2         = (const float*)d_in[8];
    const float* b2         = (const float*)d_in[9];
    const float* w_mlp1     = (const float*)d_in[10];
    const float* b_mlp1     = (const float*)d_in[11];
    const float* w_mlp2     = (const float*)d_in[12];
    const float* b_mlp2     = (const float*)d_in[13];
    float* out = (float*)d_out;

    f16 *nx, *wqkv, *wo16, *w1, *w2, *qkv, *attn, *hb;
    float *x1;
    cudaGetSymbolAddress((void**)&nx, g_nx);
    cudaGetSymbolAddress((void**)&wqkv, g_wqkv);
    cudaGetSymbolAddress((void**)&wo16, g_wo);
    cudaGetSymbolAddress((void**)&w1, g_w1);
    cudaGetSymbolAddress((void**)&w2, g_w2);
    cudaGetSymbolAddress((void**)&qkv, g_qkv);
    cudaGetSymbolAddress((void**)&attn, g_attn);
    cudaGetSymbolAddress((void**)&x1, g_x1);
    cudaGetSymbolAddress((void**)&hb, g_h);

    cudaFuncSetAttribute(gemm_tc<1>, cudaFuncAttributeMaxDynamicSharedMemorySize, SMEM_DYN);
    cudaFuncSetAttribute(gemm_tc<2>, cudaFuncAttributeMaxDynamicSharedMemorySize, SMEM_DYN);
    cudaFuncSetAttribute(gemm_tc<3>, cudaFuncAttributeMaxDynamicSharedMemorySize, SMEM_DYN);
    cudaFuncSetAttribute(gemm_tc<4>, cudaFuncAttributeMaxDynamicSharedMemorySize, SMEM_DYN);
    cudaFuncSetAttribute(flash_tc, cudaFuncAttributeMaxDynamicSharedMemorySize, FSMEM);

    dim3 gblk(256);
    dim3 fblk(128);
    dim3 blk(256);

    // 0+1. weight converts + LN1 (one launch)
    prep_kernel<<<16384, blk>>>(wq, wk, wv, wo, w_mlp1, w_mlp2,
                                wqkv, wo16, w1, w2, x, g1, b1, nx);
    // 2. qkv = nx @ wqkv^T  (768 tiles, persistent)
    gemm_tc<4><<<NPERS, gblk, SMEM_DYN>>>(
        nx, wqkv, nullptr, nullptr, nullptr, qkv, MTOK, QKVN, DIMD);
    // 3. attn = flash(qkv)
    flash_tc<<<dim3(LLEN / 64, NHEAD, BB), fblk, FSMEM>>>(qkv, sm, attn);
    // 4. x1 = x + attn @ wo^T  (256 tiles)
    gemm_tc<1><<<256, gblk, SMEM_DYN>>>(
        attn, wo16, nullptr, x, x1, nullptr, MTOK, DIMD, DIMD);
    // 5. nx = LN(x1; g2,b2)
    ln_kernel<<<MTOK, blk>>>(x1, g2, b2, nx);
    // 6. h = gelu(nx @ w1^T + b1)  (1024 tiles, persistent)
    gemm_tc<3><<<NPERS, gblk, SMEM_DYN>>>(
        nx, w1, b_mlp1, nullptr, nullptr, hb, MTOK, FFD, DIMD);
    // 7. out = x1 + h @ w2^T + b2  (256 tiles)
    gemm_tc<2><<<256, gblk, SMEM_DYN>>>(
        hb, w2, b_mlp2, x1, out, nullptr, MTOK, DIMD, FFD);
}

// round 13
// speedup vs baseline: 1.0419x; 1.0419x over previous
#include <cuda_runtime.h>
#include <cuda_fp16.h>
#include <math.h>
#include <stddef.h>
#include <stdint.h>

#define DIMD 1024
#define BB 2
#define LLEN 2048
#define MTOK 4096
#define NHEAD 16
#define HD 64
#define FFD 4096
#define QKVN 3072

typedef __half f16;

// ---------------- scratch (device globals; no allocations allowed) ----------
__device__ f16  g_nx[MTOK * DIMD];
__device__ f16  g_wqkv[QKVN * DIMD];
__device__ f16  g_wo[DIMD * DIMD];
__device__ f16  g_w1[FFD * DIMD];
__device__ f16  g_w2[DIMD * FFD];
__device__ f16  g_qkv[(size_t)MTOK * QKVN];
__device__ f16  g_attn[MTOK * DIMD];
__device__ float g_x1[MTOK * DIMD];
__device__ f16  g_h[(size_t)MTOK * FFD];

// ---------------- helpers -----------------------------------------------------
__device__ __forceinline__ uint32_t cvta_s(const void* p) {
    return (uint32_t)__cvta_generic_to_shared(p);
}
__device__ __forceinline__ void cp16(uint32_t dst, const void* src) {
    asm volatile("cp.async.cg.shared.global [%0], [%1], 16;" :: "r"(dst), "l"(src) : "memory");
}
__device__ __forceinline__ void ldm_x4(uint32_t addr, uint32_t& r0, uint32_t& r1,
                                       uint32_t& r2, uint32_t& r3) {
    asm volatile("ldmatrix.sync.aligned.m8n8.x4.shared.b16 {%0,%1,%2,%3}, [%4];"
                 : "=r"(r0), "=r"(r1), "=r"(r2), "=r"(r3) : "r"(addr));
}
__device__ __forceinline__ void ldm_x4_t(uint32_t addr, uint32_t& r0, uint32_t& r1,
                                         uint32_t& r2, uint32_t& r3) {
    asm volatile("ldmatrix.sync.aligned.m8n8.x4.trans.shared.b16 {%0,%1,%2,%3}, [%4];"
                 : "=r"(r0), "=r"(r1), "=r"(r2), "=r"(r3) : "r"(addr));
}
__device__ __forceinline__ void mma_f16(float& d0, float& d1, float& d2, float& d3,
                                        uint32_t a0, uint32_t a1, uint32_t a2, uint32_t a3,
                                        uint32_t b0, uint32_t b1) {
    asm volatile(
        "mma.sync.aligned.m16n8k16.row.col.f32.f16.f16.f32 "
        "{%0,%1,%2,%3}, {%4,%5,%6,%7}, {%8,%9}, {%0,%1,%2,%3};"
        : "+f"(d0), "+f"(d1), "+f"(d2), "+f"(d3)
        : "r"(a0), "r"(a1), "r"(a2), "r"(a3), "r"(b0), "r"(b1));
}
__device__ __forceinline__ uint32_t pack2f(float a, float b) {
    __half2 h = __floats2half2_rn(a, b);
    return *reinterpret_cast<uint32_t*>(&h);
}

// ---------------- prep: weight converts + LN1 in ONE launch -------------------
__global__ __launch_bounds__(256) void prep_kernel(
    const float* __restrict__ wq, const float* __restrict__ wk,
    const float* __restrict__ wv, const float* __restrict__ wo,
    const float* __restrict__ w1, const float* __restrict__ w2,
    f16* __restrict__ dqkv, f16* __restrict__ dwo,
    f16* __restrict__ dw1, f16* __restrict__ dw2,
    const float* __restrict__ x, const float* __restrict__ g1,
    const float* __restrict__ b1, f16* __restrict__ nx)
{
    int blk = blockIdx.x;
    int tid = threadIdx.x;
    if (blk < 12288) {
        const float* src;
        f16* dst;
        size_t off;
        const size_t DD = (size_t)DIMD * DIMD;
        if (blk < 1024)      { src = wq; dst = dqkv;          off = (size_t)blk * 1024; }
        else if (blk < 2048) { src = wk; dst = dqkv + DD;     off = (size_t)(blk - 1024) * 1024; }
        else if (blk < 3072) { src = wv; dst = dqkv + 2 * DD; off = (size_t)(blk - 2048) * 1024; }
        else if (blk < 4096) { src = wo; dst = dwo;           off = (size_t)(blk - 3072) * 1024; }
        else if (blk < 8192) { src = w1; dst = dw1;           off = (size_t)(blk - 4096) * 1024; }
        else                 { src = w2; dst = dw2;           off = (size_t)(blk - 8192) * 1024; }
        size_t i = off + tid * 4;
        float4 v = *(const float4*)(src + i);
        f16 h4[4];
        h4[0] = __float2half_rn(v.x); h4[1] = __float2half_rn(v.y);
        h4[2] = __float2half_rn(v.z); h4[3] = __float2half_rn(v.w);
        *(uint2*)(dst + i) = *(uint2*)h4;
        return;
    }
    int row = blk - 12288;
    float4 v = ((const float4*)(x + (size_t)row * DIMD))[tid];
    float s  = v.x + v.y + v.z + v.w;
    float sq = v.x * v.x + v.y * v.y + v.z * v.z + v.w * v.w;
    #pragma unroll
    for (int o = 16; o; o >>= 1) {
        s  += __shfl_xor_sync(0xFFFFFFFFu, s,  o);
        sq += __shfl_xor_sync(0xFFFFFFFFu, sq, o);
    }
    __shared__ float red[8], red2[8], mu_s, rs_s;
    int w = tid >> 5, ln = tid & 31;
    if (ln == 0) { red[w] = s; red2[w] = sq; }
    __syncthreads();
    if (tid == 0) {
        float ts = 0.f, tq = 0.f;
        #pragma unroll
        for (int i = 0; i < 8; i++) { ts += red[i]; tq += red2[i]; }
        float mu  = ts * (1.0f / DIMD);
        float var = tq * (1.0f / DIMD) - mu * mu;
        mu_s = mu;
        rs_s = rsqrtf(var + 1e-5f);
    }
    __syncthreads();
    float mu = mu_s, rs = rs_s;
    float4 gv = ((const float4*)g1)[tid];
    float4 bv = ((const float4*)b1)[tid];
    f16 h4[4];
    h4[0] = __float2half_rn((v.x - mu) * rs * gv.x + bv.x);
    h4[1] = __float2half_rn((v.y - mu) * rs * gv.y + bv.y);
    h4[2] = __float2half_rn((v.z - mu) * rs * gv.z + bv.z);
    h4[3] = __float2half_rn((v.w - mu) * rs * gv.w + bv.w);
    *(uint2*)(nx + (size_t)row * DIMD + tid * 4) = *(uint2*)h4;
}

// ---------------- LayerNorm (standalone, LN2) ---------------------------------
__global__ __launch_bounds__(256) void ln_kernel(
    const float* __restrict__ x, const float* __restrict__ g,
    const float* __restrict__ b, f16* __restrict__ ohi)
{
    int row = blockIdx.x;
    int tid = threadIdx.x;
    float4 v = ((const float4*)(x + (size_t)row * DIMD))[tid];
    float s  = v.x + v.y + v.z + v.w;
    float sq = v.x * v.x + v.y * v.y + v.z * v.z + v.w * v.w;
    #pragma unroll
    for (int o = 16; o; o >>= 1) {
        s  += __shfl_xor_sync(0xFFFFFFFFu, s,  o);
        sq += __shfl_xor_sync(0xFFFFFFFFu, sq, o);
    }
    __shared__ float red[8], red2[8], mu_s, rs_s;
    int w = tid >> 5, ln = tid & 31;
    if (ln == 0) { red[w] = s; red2[w] = sq; }
    __syncthreads();
    if (tid == 0) {
        float ts = 0.f, tq = 0.f;
        #pragma unroll
        for (int i = 0; i < 8; i++) { ts += red[i]; tq += red2[i]; }
        float mu  = ts * (1.0f / DIMD);
        float var = tq * (1.0f / DIMD) - mu * mu;
        mu_s = mu;
        rs_s = rsqrtf(var + 1e-5f);
    }
    __syncthreads();
    float mu = mu_s, rs = rs_s;
    float4 gv = ((const float4*)g)[tid];
    float4 bv = ((const float4*)b)[tid];
    f16 h4[4];
    h4[0] = __float2half_rn((v.x - mu) * rs * gv.x + bv.x);
    h4[1] = __float2half_rn((v.y - mu) * rs * gv.y + bv.y);
    h4[2] = __float2half_rn((v.z - mu) * rs * gv.z + bv.z);
    h4[3] = __float2half_rn((v.w - mu) * rs * gv.w + bv.w);
    *(uint2*)(ohi + (size_t)row * DIMD + tid * 4) = *(uint2*)h4;
}

// ---------------- HMMA fp16 GEMM: single-sync pipeline ------------------------
// Per chunk: wait -> sync -> issue loads (2 ahead) -> compute. One barrier/chunk.
// EPI: 1=f32+res  2=f32+bias+res  3=bias+gelu->f16  4=f16
#define SSTRIDE 72
#define TILE_BYTES (128 * SSTRIDE * 2)
#define STAGE_BYTES (2 * TILE_BYTES)
#define NSTAGE 3
#define SMEM_DYN (NSTAGE * STAGE_BYTES)

template <int EPI>
__global__ __launch_bounds__(256) void gemm_tc(
    const f16* __restrict__ A, const f16* __restrict__ B,
    const float* __restrict__ bias, const float* __restrict__ res,
    float* __restrict__ Cf, f16* __restrict__ Ch,
    int M, int N, int K)
{
    extern __shared__ __align__(128) char smem[];
    uint32_t sbase = cvta_s(smem);
    int tid  = threadIdx.x;
    int lane = tid & 31;
    int w    = tid >> 5;
    int warpM = w & 3, warpN = w >> 2;
    int m0 = blockIdx.y * 128, n0 = blockIdx.x * 128;

    const int C = K >> 6;

    float acc[2][8][4];
    #pragma unroll
    for (int i = 0; i < 2; i++)
        #pragma unroll
        for (int j = 0; j < 8; j++)
            #pragma unroll
            for (int t = 0; t < 4; t++) acc[i][j][t] = 0.f;

    auto load_chunk = [&](int c, int stage) {
        int k0 = c << 6;
        uint32_t abuf = sbase + stage * STAGE_BYTES;
        uint32_t bbuf = abuf + TILE_BYTES;
        #pragma unroll
        for (int i = 0; i < 4; i++) {
            int idx = tid + i * 256;
            int row = idx >> 3;
            int cg  = idx & 7;
            uint32_t doff = row * (SSTRIDE * 2) + cg * 16;
            cp16(abuf + doff, A + (size_t)(m0 + row) * K + k0 + cg * 8);
            cp16(bbuf + doff, B + (size_t)(n0 + row) * K + k0 + cg * 8);
        }
        asm volatile("cp.async.commit_group;");
    };

    load_chunk(0, 0);
    load_chunk(1, 1);

    int lrow = lane & 15;
    int lcol = (lane >> 4) << 3;

    for (int c = 0; c < C; c++) {
        // chunk c guaranteed landed: only chunk c+1 may remain in flight
        if (c == C - 1) asm volatile("cp.async.wait_group 0;" ::: "memory");
        else            asm volatile("cp.async.wait_group 1;" ::: "memory");
        __syncthreads();                     // also: stage (c-1)%3 free for reuse
        if (c + 2 < C) {
            int st = (c + 2) % NSTAGE;
            load_chunk(c + 2, st);           // loads in flight DURING compute
        }
        int stage = c % NSTAGE;
        uint32_t abuf = sbase + stage * STAGE_BYTES;
        uint32_t bbuf = abuf + TILE_BYTES;

        #pragma unroll
        for (int ks = 0; ks < 4; ks++) {
            int kk = ks * 16;
            uint32_t a[2][4];
            #pragma unroll
            for (int mi = 0; mi < 2; mi++) {
                int r = warpM * 32 + mi * 16 + lrow;
                uint32_t addr = abuf + (r * SSTRIDE + kk + lcol) * 2;
                ldm_x4(addr, a[mi][0], a[mi][1], a[mi][2], a[mi][3]);
            }
            uint32_t bfr[8][2];
            #pragma unroll
            for (int nj = 0; nj < 4; nj++) {
                int r = warpN * 64 + nj * 16 + lrow;
                uint32_t addr = bbuf + (r * SSTRIDE + kk + lcol) * 2;
                uint32_t b0, b1, b2, b3;
                ldm_x4(addr, b0, b1, b2, b3);
                bfr[nj * 2 + 0][0] = b0; bfr[nj * 2 + 0][1] = b2;
                bfr[nj * 2 + 1][0] = b1; bfr[nj * 2 + 1][1] = b3;
            }
            #pragma unroll
            for (int mi = 0; mi < 2; mi++)
                #pragma unroll
                for (int nt = 0; nt < 8; nt++)
                    mma_f16(acc[mi][nt][0], acc[mi][nt][1], acc[mi][nt][2], acc[mi][nt][3],
                            a[mi][0], a[mi][1], a[mi][2], a[mi][3],
                            bfr[nt][0], bfr[nt][1]);
        }
    }

    int rbase = m0 + warpM * 32 + (lane >> 2);
    int cbase = n0 + warpN * 64 + (lane & 3) * 2;

    #pragma unroll
    for (int mi = 0; mi < 2; mi++) {
        #pragma unroll
        for (int half = 0; half < 2; half++) {
            int row = rbase + mi * 16 + half * 8;
            size_t gr = (size_t)row * N;
            #pragma unroll
            for (int nt = 0; nt < 8; nt++) {
                int col = cbase + nt * 8;
                float v0 = acc[mi][nt][half * 2 + 0];
                float v1 = acc[mi][nt][half * 2 + 1];
                if (EPI == 2 || EPI == 3) { v0 += bias[col]; v1 += bias[col + 1]; }
                if (EPI == 3 || EPI == 4) {
                    if (EPI == 3) {
                        v0 = 0.5f * v0 * (1.f + erff(v0 * 0.70710678118654752f));
                        v1 = 0.5f * v1 * (1.f + erff(v1 * 0.70710678118654752f));
                    }
                    *(uint32_t*)(Ch + gr + col) = pack2f(v0, v1);
                } else {
                    float2 rr = *(const float2*)(res + gr + col);
                    v0 += rr.x; v1 += rr.y;
                    *(float2*)(Cf + gr + col) = make_float2(v0, v1);
                }
            }
        }
    }
}

// ---------------- HMMA flash attention: fixed-shift softmax -------------------
#define KSTRB 144
#define FTILE (64 * KSTRB)
#define FS_Q0   0
#define FS_STG  FTILE
#define FS_BIAS (FS_STG + 2 * 2 * FTILE)
#define FSMEM   (FS_BIAS + LLEN * 4)
#define C2EXP   0.1803368801111204f
#define LOG2E   1.4426950408889634f

__global__ __launch_bounds__(128) void flash_tc(
    const f16* __restrict__ qkv, const unsigned char* __restrict__ smask,
    f16* __restrict__ oh)
{
    extern __shared__ __align__(128) char sm[];
    uint32_t sb = cvta_s(sm);
    float* biasArr = (float*)(sm + FS_BIAS);
    int qt = gridDim.x - 1 - blockIdx.x;
    int h = blockIdx.y, b = blockIdx.z;
    int tid = threadIdx.x, lane = tid & 31, w = tid >> 5;
    int lrow = lane & 15, lcol = (lane >> 4) << 3;
    size_t tok0 = (size_t)b * LLEN;
    int hoff = h * HD;

    #pragma unroll
    for (int i = 0; i < 4; i++) {
        int slot = tid + i * 128;
        int r    = slot >> 3;
        int seg  = slot & 7;
        const f16* src = qkv + (tok0 + qt * 64 + r) * QKVN + hoff + seg * 8;
        cp16(sb + FS_Q0 + r * KSTRB + seg * 16, src);
    }
    asm volatile("cp.async.commit_group;");

    for (int i = tid; i < LLEN; i += 128) {
        float m = smask[tok0 + i] ? -10003.f : -3.f;
        biasArr[i] = m * LOG2E;
    }

    auto load_stage = [&](int kt, int s) {
        uint32_t base = sb + FS_STG + s * (2 * FTILE);
        int k0 = kt * 64;
        #pragma unroll
        for (int i = 0; i < 8; i++) {
            int slot = tid + i * 128;
            int comp = slot >> 9;
            int r    = (slot >> 3) & 63;
            int seg  = slot & 7;
            int coff = comp ? 2 * DIMD : DIMD;
            const f16* src = qkv + (tok0 + k0 + r) * QKVN + coff + hoff + seg * 8;
            cp16(base + comp * FTILE + r * KSTRB + seg * 16, src);
        }
        asm volatile("cp.async.commit_group;");
    };

    load_stage(0, 0);

    asm volatile("cp.async.wait_group 1;" ::: "memory");
    __syncthreads();

    uint32_t qf[4][4];
    #pragma unroll
    for (int kc = 0; kc < 4; kc++) {
        uint32_t addr = sb + FS_Q0 + (w * 16 + lrow) * KSTRB + (kc * 16 + lcol) * 2;
        ldm_x4(addr, qf[kc][0], qf[kc][1], qf[kc][2], qf[kc][3]);
    }

    float O[8][4];
    #pragma unroll
    for (int nt = 0; nt < 8; nt++)
        #pragma unroll
        for (int t = 0; t < 4; t++) O[nt][t] = 0.f;
    float l0r = 0.f, l1r = 0.f;

    int colb = 2 * (lane & 3);
    int qrow0 = qt * 64 + w * 16 + (lane >> 2);
    int qrow1 = qrow0 + 8;

    for (int kt = 0; kt <= qt; kt++) {
        int s = kt & 1;
        if (kt < qt) {
            load_stage(kt + 1, s ^ 1);
            asm volatile("cp.async.wait_group 1;" ::: "memory");
        } else {
            asm volatile("cp.async.wait_group 0;" ::: "memory");
        }
        __syncthreads();

        uint32_t KHB = sb + FS_STG + s * (2 * FTILE);
        uint32_t VHB = KHB + FTILE;
        bool diag = (kt == qt);

        float S[8][4];
        #pragma unroll
        for (int nt = 0; nt < 8; nt++)
            #pragma unroll
            for (int t = 0; t < 4; t++) S[nt][t] = 0.f;

        #pragma unroll
        for (int kc = 0; kc < 4; kc++) {
            uint32_t bh[8][2];
            #pragma unroll
            for (int nj = 0; nj < 4; nj++) {
                uint32_t addr = KHB + (nj * 16 + lrow) * KSTRB + (kc * 16 + lcol) * 2;
                uint32_t r0, r1, r2, r3;
                ldm_x4(addr, r0, r1, r2, r3);
                bh[nj * 2][0] = r0; bh[nj * 2][1] = r2;
                bh[nj * 2 + 1][0] = r1; bh[nj * 2 + 1][1] = r3;
            }
            #pragma unroll
            for (int nt = 0; nt < 8; nt++)
                mma_f16(S[nt][0], S[nt][1], S[nt][2], S[nt][3],
                        qf[kc][0], qf[kc][1], qf[kc][2], qf[kc][3],
                        bh[nt][0], bh[nt][1]);
        }

        uint32_t ph[8][2];
        #pragma unroll
        for (int nt = 0; nt < 8; nt++) {
            int c0 = kt * 64 + nt * 8 + colb;
            float2 bz = *(const float2*)&biasArr[c0];
            float p0 = exp2f(fmaf(S[nt][0], C2EXP, bz.x));
            float p1 = exp2f(fmaf(S[nt][1], C2EXP, bz.y));
            float p2 = exp2f(fmaf(S[nt][2], C2EXP, bz.x));
            float p3 = exp2f(fmaf(S[nt][3], C2EXP, bz.y));
            if (diag) {
                p0 = (c0     <= qrow0) ? p0 : 0.f;
                p1 = (c0 + 1 <= qrow0) ? p1 : 0.f;
                p2 = (c0     <= qrow1) ? p2 : 0.f;
                p3 = (c0 + 1 <= qrow1) ? p3 : 0.f;
            }
            l0r += p0 + p1;
            l1r += p2 + p3;
            ph[nt][0] = pack2f(p0, p1);
            ph[nt][1] = pack2f(p2, p3);
        }

        #pragma unroll
        for (int kc = 0; kc < 4; kc++) {
            uint32_t ah0 = ph[2 * kc][0], ah1 = ph[2 * kc][1];
            uint32_t ah2 = ph[2 * kc + 1][0], ah3 = ph[2 * kc + 1][1];
            #pragma unroll
            for (int dn = 0; dn < 4; dn++) {
                int g = lane >> 3, j = lane & 7;
                uint32_t addr = VHB + (kc * 16 + ((g & 1) ? 8 : 0) + j) * KSTRB
                              + (dn * 16 + ((g >> 1) ? 8 : 0)) * 2;
                uint32_t vh0, vh1, vh2, vh3;
                ldm_x4_t(addr, vh0, vh1, vh2, vh3);
                mma_f16(O[2 * dn][0], O[2 * dn][1], O[2 * dn][2], O[2 * dn][3],
                        ah0, ah1, ah2, ah3, vh0, vh1);
                mma_f16(O[2 * dn + 1][0], O[2 * dn + 1][1], O[2 * dn + 1][2], O[2 * dn + 1][3],
                        ah0, ah1, ah2, ah3, vh2, vh3);
            }
        }
        __syncthreads();
    }

    l0r += __shfl_xor_sync(0xFFFFFFFFu, l0r, 1);
    l0r += __shfl_xor_sync(0xFFFFFFFFu, l0r, 2);
    l1r += __shfl_xor_sync(0xFFFFFFFFu, l1r, 1);
    l1r += __shfl_xor_sync(0xFFFFFFFFu, l1r, 2);
    float i0 = 1.f / l0r, i1 = 1.f / l1r;
    size_t t0k = tok0 + qt * 64 + w * 16 + (lane >> 2);
    size_t t1k = t0k + 8;
    #pragma unroll
    for (int nt = 0; nt < 8; nt++) {
        int col = hoff + nt * 8 + colb;
        *(uint32_t*)(oh + t0k * DIMD + col) = pack2f(O[nt][0] * i0, O[nt][1] * i0);
        *(uint32_t*)(oh + t1k * DIMD + col) = pack2f(O[nt][2] * i1, O[nt][3] * i1);
    }
}

// ---------------- driver -----------------------------------------------------
extern "C" void kernel_launch(void* const* d_in, const int* in_sizes, int n_in,
                              void* d_out, int out_size)
{
    const float* x          = (const float*)d_in[0];
    const unsigned char* sm = (const unsigned char*)d_in[1];
    const float* wq         = (const float*)d_in[2];
    const float* wk         = (const float*)d_in[3];
    const float* wv         = (const float*)d_in[4];
    const float* wo         = (const float*)d_in[5];
    const float* g1         = (const float*)d_in[6];
    const float* b1         = (const float*)d_in[7];
    const float* g2         = (const float*)d_in[8];
    const float* b2         = (const float*)d_in[9];
    const float* w_mlp1     = (const float*)d_in[10];
    const float* b_mlp1     = (const float*)d_in[11];
    const float* w_mlp2     = (const float*)d_in[12];
    const float* b_mlp2     = (const float*)d_in[13];
    float* out = (float*)d_out;

    f16 *nx, *wqkv, *wo16, *w1, *w2, *qkv, *attn, *hb;
    float *x1;
    cudaGetSymbolAddress((void**)&nx, g_nx);
    cudaGetSymbolAddress((void**)&wqkv, g_wqkv);
    cudaGetSymbolAddress((void**)&wo16, g_wo);
    cudaGetSymbolAddress((void**)&w1, g_w1);
    cudaGetSymbolAddress((void**)&w2, g_w2);
    cudaGetSymbolAddress((void**)&qkv, g_qkv);
    cudaGetSymbolAddress((void**)&attn, g_attn);
    cudaGetSymbolAddress((void**)&x1, g_x1);
    cudaGetSymbolAddress((void**)&hb, g_h);

    cudaFuncSetAttribute(gemm_tc<1>, cudaFuncAttributeMaxDynamicSharedMemorySize, SMEM_DYN);
    cudaFuncSetAttribute(gemm_tc<2>, cudaFuncAttributeMaxDynamicSharedMemorySize, SMEM_DYN);
    cudaFuncSetAttribute(gemm_tc<3>, cudaFuncAttributeMaxDynamicSharedMemorySize, SMEM_DYN);
    cudaFuncSetAttribute(gemm_tc<4>, cudaFuncAttributeMaxDynamicSharedMemorySize, SMEM_DYN);
    cudaFuncSetAttribute(flash_tc, cudaFuncAttributeMaxDynamicSharedMemorySize, FSMEM);

    dim3 gblk(256);
    dim3 fblk(128);
    dim3 blk(256);

    // 0+1. weight converts + LN1 (one launch)
    prep_kernel<<<16384, blk>>>(wq, wk, wv, wo, w_mlp1, w_mlp2,
                                wqkv, wo16, w1, w2, x, g1, b1, nx);
    // 2. qkv = nx @ wqkv^T
    gemm_tc<4><<<dim3(QKVN / 128, MTOK / 128), gblk, SMEM_DYN>>>(
        nx, wqkv, nullptr, nullptr, nullptr, qkv, MTOK, QKVN, DIMD);
    // 3. attn = flash(qkv)
    flash_tc<<<dim3(LLEN / 64, NHEAD, BB), fblk, FSMEM>>>(qkv, sm, attn);
    // 4. x1 = x + attn @ wo^T
    gemm_tc<1><<<dim3(DIMD / 128, MTOK / 128), gblk, SMEM_DYN>>>(
        attn, wo16, nullptr, x, x1, nullptr, MTOK, DIMD, DIMD);
    // 5. nx = LN(x1; g2,b2)
    ln_kernel<<<MTOK, blk>>>(x1, g2, b2, nx);
    // 6. h = gelu(nx @ w1^T + b1)
    gemm_tc<3><<<dim3(FFD / 128, MTOK / 128), gblk, SMEM_DYN>>>(
        nx, w1, b_mlp1, nullptr, nullptr, hb, MTOK, FFD, DIMD);
    // 7. out = x1 + h @ w2^T + b2
    gemm_tc<2><<<dim3(DIMD / 128, MTOK / 128), gblk, SMEM_DYN>>>(
        hb, w2, b_mlp2, x1, out, nullptr, MTOK, DIMD, FFD);
}